// round 13
// baseline (speedup 1.0000x reference)
#include <cuda_runtime.h>
#include <cuda_fp16.h>
#include <stdint.h>

#define DEVI static __device__ __forceinline__

#define BATCH 512
#define DIM   512
#define NCLS  100000
#define NTILES 782            // ceil(100000/128); last tile overlaps (n0 = 99872)

static constexpr float C_SCALE  = 64.0f;
static constexpr float C_ALPHA  = 1.2f;
static constexpr float C_COSM   =  0.87758256189037271612f;  // cos(0.5)
static constexpr float C_SINM   =  0.47942553860420300027f;  // sin(0.5)
static constexpr float C_THRESH = -0.87758256189037271612f;  // cos(pi-0.5)
static constexpr float C_MM     =  0.23971276930210150013f;  // sin(0.5)*0.5

// SMEM: 2 stages x (A 16KB + B 32KB) = 98304, then norm[128] floats
#define STAGE_BYTES 49152
#define SM_NORM     98304
#define SM_TOTAL    (98304 + 512)

// ---- device-global scratch (no allocation allowed) ----
__device__ __align__(1024) __half g_Ah[BATCH * DIM];
__device__ float g_target[BATCH];
__device__ int   g_label[BATCH];

// ---------------- PTX helpers ----------------
DEVI uint32_t smem_u32(const void* p) {
    uint32_t a;
    asm("{ .reg .u64 t; cvta.to.shared.u64 t, %1; cvt.u32.u64 %0, t; }" : "=r"(a) : "l"(p));
    return a;
}
DEVI void cp_async16(uint32_t dst, const void* src) {
    asm volatile("cp.async.cg.shared.global [%0], [%1], 16;" :: "r"(dst), "l"(src) : "memory");
}
DEVI void cp_commit() { asm volatile("cp.async.commit_group;" ::: "memory"); }
template <int N> DEVI void cp_wait() {
    asm volatile("cp.async.wait_group %0;" :: "n"(N) : "memory");
}
DEVI void ldsm_x4(uint32_t* r, uint32_t addr) {
    asm volatile("ldmatrix.sync.aligned.m8n8.x4.shared.b16 {%0,%1,%2,%3}, [%4];"
                 : "=r"(r[0]), "=r"(r[1]), "=r"(r[2]), "=r"(r[3]) : "r"(addr));
}
DEVI void lds_v2f32(float& lo, float& hi, uint32_t addr) {
    asm volatile("ld.shared.v2.f32 {%0,%1}, [%2];" : "=f"(lo), "=f"(hi) : "r"(addr));
}
DEVI uint32_t pack_f16x2(float lo, float hi) {
    uint32_t d;
    asm("cvt.rn.f16x2.f32 %0, %1, %2;" : "=r"(d) : "f"(hi), "f"(lo));  // %1 -> high half
    return d;
}
DEVI void mma16816(float* d, const uint32_t* a, uint32_t b0, uint32_t b1) {
    asm volatile(
        "mma.sync.aligned.m16n8k16.row.col.f32.f16.f16.f32 "
        "{%0,%1,%2,%3}, {%4,%5,%6,%7}, {%8,%9}, {%0,%1,%2,%3};"
        : "+f"(d[0]), "+f"(d[1]), "+f"(d[2]), "+f"(d[3])
        : "r"(a[0]), "r"(a[1]), "r"(a[2]), "r"(a[3]), "r"(b0), "r"(b1));
}

// ---------------- kernel 1: prep (label fix + norm_x + exact fp32 target) ----------------
__global__ void prep_kernel(const float* __restrict__ x,
                            const int* __restrict__ lraw,
                            const float* __restrict__ w)
{
    __shared__ int s_or;
    const int tid  = threadIdx.x;
    const int wid  = tid >> 5;
    const int lane = tid & 31;
    const int b    = blockIdx.x * 8 + wid;

    if (tid == 0) s_or = 0;
    __syncthreads();
    if (tid < 256) {
        if (lraw[2 * tid + 1] != 0) atomicOr(&s_or, 1);
    }
    __syncthreads();
    const int lb = s_or ? lraw[b] : lraw[2 * b];   // int32 vs int64 low word
    if (lane == 0) g_label[b] = lb;

    const float4* xp = (const float4*)(x + (size_t)b * DIM);
    const float4* wp = (const float4*)(w + (size_t)lb * DIM);
    float4 v[4];
    float xx = 0.f, ww = 0.f, xw = 0.f;
#pragma unroll
    for (int i = 0; i < 4; i++) {
        v[i] = xp[lane + 32 * i];
        float4 c = wp[lane + 32 * i];
        xx += v[i].x * v[i].x + v[i].y * v[i].y + v[i].z * v[i].z + v[i].w * v[i].w;
        ww += c.x * c.x + c.y * c.y + c.z * c.z + c.w * c.w;
        xw += v[i].x * c.x + v[i].y * c.y + v[i].z * c.z + v[i].w * c.w;
    }
#pragma unroll
    for (int o = 16; o > 0; o >>= 1) {
        xx += __shfl_xor_sync(0xFFFFFFFFu, xx, o);
        ww += __shfl_xor_sync(0xFFFFFFFFu, ww, o);
        xw += __shfl_xor_sync(0xFFFFFFFFu, xw, o);
    }

    float rx = rsqrtf(xx);
    rx = rx * (1.5f - 0.5f * xx * rx * rx);   // NR refine
    uint2* dp = (uint2*)(g_Ah + (size_t)b * DIM);
#pragma unroll
    for (int i = 0; i < 4; i++) {
        __half h0 = __float2half_rn(v[i].x * rx);
        __half h1 = __float2half_rn(v[i].y * rx);
        __half h2 = __float2half_rn(v[i].z * rx);
        __half h3 = __float2half_rn(v[i].w * rx);
        __half2 p01 = __halves2half2(h0, h1);
        __half2 p23 = __halves2half2(h2, h3);
        uint2 u;
        u.x = *(uint32_t*)&p01;
        u.y = *(uint32_t*)&p23;
        dp[lane + 32 * i] = u;
    }

    if (lane == 0) {
        float p = xx * ww;
        float r = rsqrtf(p);
        r = r * (1.5f - 0.5f * p * r * r);
        float c = xw * r;
        float tgt = (c > C_THRESH)
                        ? (c * C_COSM - C_SINM * sqrtf(fmaxf(1.f - c * c, 0.f)))
                        : (c - C_MM);
        g_target[b] = tgt;
    }
}

// ---------------- kernel 2: GEMM on raw fp32 w + inline norm + fused epilogue ----------------
// CTA tile 128M x 128N, K=512 in 8 chunks of 64, 2-stage cp.async pipeline.
// A: normalized fp16 (g_Ah) via cp.async + ldsm (as before).
// B: RAW fp32 w via cp.async; fragments built with ld.shared.v2.f32 + cvt to f16x2.
// Per-column sumsq accumulated in-register (wm==0 warps) during the mainloop;
// epilogue scales cos by rsqrt(sumsq[col]). No separate w pass at all.
__global__ __launch_bounds__(256, 2)
void gemm_kernel(const float* __restrict__ w, float* __restrict__ out)
{
    extern __shared__ char smem[];
    const uint32_t sbase = smem_u32(smem);
    const int tid  = threadIdx.x;
    const int wid  = tid >> 5;
    const int lane = tid & 31;
    const int m0   = blockIdx.x * 128;   // 4 m-tiles fastest -> share B tile in L2
    int n0 = blockIdx.y * 128;
    if (n0 > NCLS - 128) n0 = NCLS - 128;   // overlapped last tile, no OOB anywhere
    const int wm   = (wid & 1) * 64;
    const int wn   = (wid >> 1) * 32;

    const char* Ag = (const char*)g_Ah;

    float acc[4][4][4];
#pragma unroll
    for (int mt = 0; mt < 4; mt++)
#pragma unroll
        for (int nt = 0; nt < 4; nt++)
#pragma unroll
            for (int i = 0; i < 4; i++) acc[mt][nt][i] = 0.f;

    float sq[4] = {0.f, 0.f, 0.f, 0.f};   // per-thread partial sumsq (wm==0 warps)

    // ---- A loader constants (fp16, 16B granules, XOR-16B swizzle over 128B rows) ----
    const int aw_row = tid >> 3;          // 0..31
    const int aw_c   = tid & 7;
    const uint32_t a_soff0 = (uint32_t)(aw_row * 128 + ((aw_c ^ (aw_row & 7)) << 4));
    const size_t a_ga = (size_t)(m0 + aw_row) * 512 + aw_c * 8;

    // ---- B loader constants (fp32, 16B granules, XOR-32B swizzle over 256B rows) ----
    const int bw_row0 = tid >> 4;         // 0..15
    const int bw_s16  = tid & 15;
    const uint32_t b_swzS = (uint32_t)((bw_row0 & 7) << 5);   // (row&7) invariant over +16*it
    const uint32_t b_soff0 = (uint32_t)(bw_row0 * 256 + ((bw_s16 << 4) ^ b_swzS));

    auto load_chunk = [&](uint32_t sA, int kc) {
        const uint32_t sB = sA + 16384;
#pragma unroll
        for (int it = 0; it < 4; it++) {
            uint32_t soff = a_soff0 + (uint32_t)(32 * it * 128);
            cp_async16(sA + soff, Ag + (a_ga + (size_t)(32 * it) * 512 + kc * 64) * 2);
        }
#pragma unroll
        for (int it = 0; it < 8; it++) {
            uint32_t soff = b_soff0 + (uint32_t)(16 * it * 256);
            cp_async16(sB + soff,
                       (const void*)(w + (size_t)(n0 + bw_row0 + 16 * it) * 512
                                       + kc * 64 + bw_s16 * 4));
        }
        cp_commit();
    };

    // ---- B fragment constants ----
    const uint32_t b_swzR = (uint32_t)((lane >> 2) << 5);     // nB&7 == lane>>2
    const uint32_t b_klo  = (uint32_t)((lane & 3) * 8);
    uint32_t rowoff[4];
#pragma unroll
    for (int nt = 0; nt < 4; nt++)
        rowoff[nt] = (uint32_t)((wn + nt * 8 + (lane >> 2)) * 256);

    load_chunk(sbase, 0);

#pragma unroll
    for (int kc = 0; kc < 8; kc++) {
        const uint32_t sA = sbase + (uint32_t)((kc & 1) * STAGE_BYTES);
        const uint32_t sB = sA + 16384;
        cp_wait<0>();
        __syncthreads();
        if (kc < 7)
            load_chunk(sbase + (uint32_t)(((kc + 1) & 1) * STAGE_BYTES), kc + 1);

#pragma unroll
        for (int ks = 0; ks < 4; ks++) {
            uint32_t a[4][4];
#pragma unroll
            for (int mt = 0; mt < 4; mt++) {
                int row = wm + mt * 16 + (lane & 15);
                int gr  = ks * 2 + (lane >> 4);
                ldsm_x4(a[mt], sA + row * 128 + (((uint32_t)gr ^ (row & 7)) << 4));
            }
            const uint32_t off0 = ((uint32_t)(64 * ks) + b_klo) ^ b_swzR;
#pragma unroll
            for (int nt = 0; nt < 4; nt++) {
                float lo0, hi0, lo1, hi1;
                const uint32_t ad = sB + rowoff[nt] + off0;
                lds_v2f32(lo0, hi0, ad);        // k, k+1
                lds_v2f32(lo1, hi1, ad ^ 32);   // k+8, k+9
                const uint32_t b0 = pack_f16x2(lo0, hi0);
                const uint32_t b1 = pack_f16x2(lo1, hi1);
                if ((wid & 1) == 0)
                    sq[nt] = fmaf(lo0, lo0, fmaf(hi0, hi0,
                              fmaf(lo1, lo1, fmaf(hi1, hi1, sq[nt]))));
#pragma unroll
                for (int mt = 0; mt < 4; mt++)
                    mma16816(acc[mt][nt], a[mt], b0, b1);
            }
        }
    }

    // ---- finalize per-column inverse norms (wm==0 warps cover all 128 cols) ----
    if ((wid & 1) == 0) {
#pragma unroll
        for (int nt = 0; nt < 4; nt++) {
            float s = sq[nt];
            s += __shfl_xor_sync(0xFFFFFFFFu, s, 1);
            s += __shfl_xor_sync(0xFFFFFFFFu, s, 2);
            if ((lane & 3) == 0) {
                float r = rsqrtf(s);
                r = r * (1.5f - 0.5f * s * r * r);
                *(float*)(smem + SM_NORM + (wn + nt * 8 + (lane >> 2)) * 4) = r;
            }
        }
    }
    __syncthreads();

    // ---- fused ArcNegFace epilogue with per-column norm scale ----
#pragma unroll
    for (int mt = 0; mt < 4; mt++) {
        const int r0 = m0 + wm + mt * 16 + (lane >> 2);
        const int r1 = r0 + 8;
        const float tg0 = g_target[r0], tg1 = g_target[r1];
        const int lb0 = g_label[r0],  lb1 = g_label[r1];
        float* o0 = out + (size_t)r0 * NCLS;
        float* o1 = out + (size_t)r1 * NCLS;
#pragma unroll
        for (int nt = 0; nt < 4; nt++) {
            const int ct = wn + nt * 8 + 2 * (lane & 3);   // col within tile (even)
            const int c0 = n0 + ct;
            const float2 nv = *(const float2*)(smem + SM_NORM + ct * 4);
            float v[4];
#pragma unroll
            for (int i = 0; i < 4; i++) {
                const float cs  = acc[mt][nt][i] * ((i & 1) ? nv.y : nv.x);
                const float tg  = (i < 2) ? tg0 : tg1;
                const int   lb  = (i < 2) ? lb0 : lb1;
                const float dd  = cs - tg;
                const float ts  = C_ALPHA * __expf(-0.5f * dd * dd);
                float r = C_SCALE * (ts * cs + ts - 1.0f);
                if (c0 + (i & 1) == lb) r = C_SCALE * tg;
                v[i] = r;
            }
            *(float2*)(o0 + c0) = make_float2(v[0], v[1]);
            *(float2*)(o1 + c0) = make_float2(v[2], v[3]);
        }
    }
}

// ---------------- launcher (2 launches, single stream) ----------------
extern "C" void kernel_launch(void* const* d_in, const int* in_sizes, int n_in,
                              void* d_out, int out_size)
{
    const float* x     = (const float*)d_in[0];
    const int*   lraw  = (const int*)d_in[1];
    const float* w     = (const float*)d_in[2];
    float*       out   = (float*)d_out;

    cudaFuncSetAttribute(gemm_kernel, cudaFuncAttributeMaxDynamicSharedMemorySize, SM_TOTAL);

    prep_kernel<<<BATCH / 8, 256>>>(x, lraw, w);

    dim3 grid(4, NTILES);
    gemm_kernel<<<grid, 256, SM_TOTAL>>>(w, out);
}

// round 14
// speedup vs baseline: 1.1132x; 1.1132x over previous
#include <cuda_runtime.h>
#include <cuda_fp16.h>
#include <stdint.h>

#define DEVI static __device__ __forceinline__

#define BATCH 512
#define DIM   512
#define NCLS  100000
#define NTILES 782            // ceil(100000/128); last tile overlaps (n0 = 99872)
#define NGEMM (NTILES * 4)    // 3128 tiles
#define PERSIST_CTAS 296      // 2 per SM x 148
#define NORMW_CTAS 12500      // NCLS/8 rows per CTA (8 warps x 1 row)

static constexpr float C_SCALE  = 64.0f;
static constexpr float C_ALPHA  = 1.2f;
static constexpr float C_COSM   =  0.87758256189037271612f;  // cos(0.5)
static constexpr float C_SINM   =  0.47942553860420300027f;  // sin(0.5)
static constexpr float C_THRESH = -0.87758256189037271612f;  // cos(pi-0.5)
static constexpr float C_MM     =  0.23971276930210150013f;  // sin(0.5)*0.5

// ---- device-global scratch (no allocation allowed) ----
__device__ __align__(1024) __half g_Ah[BATCH * DIM];
__device__ __align__(1024) __half g_Bh[(size_t)NCLS * DIM];
__device__ float g_target[BATCH];
__device__ int   g_label[BATCH];
__device__ int   g_ctr;

// ---------------- PTX helpers ----------------
DEVI uint32_t smem_u32(const void* p) {
    uint32_t a;
    asm("{ .reg .u64 t; cvta.to.shared.u64 t, %1; cvt.u32.u64 %0, t; }" : "=r"(a) : "l"(p));
    return a;
}
DEVI void cp_async16(uint32_t dst, const void* src) {
    asm volatile("cp.async.cg.shared.global [%0], [%1], 16;" :: "r"(dst), "l"(src) : "memory");
}
DEVI void cp_commit() { asm volatile("cp.async.commit_group;" ::: "memory"); }
template <int N> DEVI void cp_wait() {
    asm volatile("cp.async.wait_group %0;" :: "n"(N) : "memory");
}
DEVI void ldsm_x4(uint32_t* r, uint32_t addr) {
    asm volatile("ldmatrix.sync.aligned.m8n8.x4.shared.b16 {%0,%1,%2,%3}, [%4];"
                 : "=r"(r[0]), "=r"(r[1]), "=r"(r[2]), "=r"(r[3]) : "r"(addr));
}
DEVI void mma16816(float* d, const uint32_t* a, uint32_t b0, uint32_t b1) {
    asm volatile(
        "mma.sync.aligned.m16n8k16.row.col.f32.f16.f16.f32 "
        "{%0,%1,%2,%3}, {%4,%5,%6,%7}, {%8,%9}, {%0,%1,%2,%3};"
        : "+f"(d[0]), "+f"(d[1]), "+f"(d[2]), "+f"(d[3])
        : "r"(a[0]), "r"(a[1]), "r"(a[2]), "r"(a[3]), "r"(b0), "r"(b1));
}
DEVI void norm_row_store(const float4* sp, __half* dst, int lane) {
    float4 v[4];
    float ss = 0.f;
#pragma unroll
    for (int i = 0; i < 4; i++) {
        v[i] = sp[lane + 32 * i];
        ss += v[i].x * v[i].x + v[i].y * v[i].y + v[i].z * v[i].z + v[i].w * v[i].w;
    }
#pragma unroll
    for (int o = 16; o > 0; o >>= 1) ss += __shfl_xor_sync(0xFFFFFFFFu, ss, o);
    float r = rsqrtf(ss);
    r = r * (1.5f - 0.5f * ss * r * r);   // NR refine -> ~fp32 exact
    uint2* dp = (uint2*)dst;
#pragma unroll
    for (int i = 0; i < 4; i++) {
        __half h0 = __float2half_rn(v[i].x * r);
        __half h1 = __float2half_rn(v[i].y * r);
        __half h2 = __float2half_rn(v[i].z * r);
        __half h3 = __float2half_rn(v[i].w * r);
        __half2 p01 = __halves2half2(h0, h1);
        __half2 p23 = __halves2half2(h2, h3);
        uint2 u;
        u.x = *(uint32_t*)&p01;
        u.y = *(uint32_t*)&p23;
        dp[lane + 32 * i] = u;
    }
}

// ---------------- kernel 1: norm_w (blocks 0..12499) + prep (blocks 12500..12563) ----------------
__global__ void prep_norm_kernel(const float* __restrict__ w,
                                 const float* __restrict__ x,
                                 const int* __restrict__ lraw)
{
    const int tid  = threadIdx.x;
    const int wid  = tid >> 5;
    const int lane = tid & 31;

    if (blockIdx.x < NORMW_CTAS) {
        const int row = blockIdx.x * 8 + wid;
        if (row < NCLS)
            norm_row_store((const float4*)(w + (size_t)row * DIM),
                           g_Bh + (size_t)row * DIM, lane);
        return;
    }

    // ---- prep path: counter reset + label fix + norm_x + exact fp32 target ----
    __shared__ int s_or;
    const int b = (blockIdx.x - NORMW_CTAS) * 8 + wid;
    if (blockIdx.x == NORMW_CTAS && tid == 0) g_ctr = 0;

    if (tid == 0) s_or = 0;
    __syncthreads();
    if (tid < 256) {
        if (lraw[2 * tid + 1] != 0) atomicOr(&s_or, 1);
    }
    __syncthreads();
    const int lb = s_or ? lraw[b] : lraw[2 * b];   // int32 vs int64 low word
    if (lane == 0) g_label[b] = lb;

    const float4* xp = (const float4*)(x + (size_t)b * DIM);
    const float4* wp = (const float4*)(w + (size_t)lb * DIM);
    float4 v[4];
    float xx = 0.f, ww = 0.f, xw = 0.f;
#pragma unroll
    for (int i = 0; i < 4; i++) {
        v[i] = xp[lane + 32 * i];
        float4 c = wp[lane + 32 * i];
        xx += v[i].x * v[i].x + v[i].y * v[i].y + v[i].z * v[i].z + v[i].w * v[i].w;
        ww += c.x * c.x + c.y * c.y + c.z * c.z + c.w * c.w;
        xw += v[i].x * c.x + v[i].y * c.y + v[i].z * c.z + v[i].w * c.w;
    }
#pragma unroll
    for (int o = 16; o > 0; o >>= 1) {
        xx += __shfl_xor_sync(0xFFFFFFFFu, xx, o);
        ww += __shfl_xor_sync(0xFFFFFFFFu, ww, o);
        xw += __shfl_xor_sync(0xFFFFFFFFu, xw, o);
    }

    float rx = rsqrtf(xx);
    rx = rx * (1.5f - 0.5f * xx * rx * rx);
    uint2* dp = (uint2*)(g_Ah + (size_t)b * DIM);
#pragma unroll
    for (int i = 0; i < 4; i++) {
        __half h0 = __float2half_rn(v[i].x * rx);
        __half h1 = __float2half_rn(v[i].y * rx);
        __half h2 = __float2half_rn(v[i].z * rx);
        __half h3 = __float2half_rn(v[i].w * rx);
        __half2 p01 = __halves2half2(h0, h1);
        __half2 p23 = __halves2half2(h2, h3);
        uint2 u;
        u.x = *(uint32_t*)&p01;
        u.y = *(uint32_t*)&p23;
        dp[lane + 32 * i] = u;
    }

    if (lane == 0) {
        float p = xx * ww;
        float r = rsqrtf(p);
        r = r * (1.5f - 0.5f * p * r * r);
        float c = xw * r;
        float tgt = (c > C_THRESH)
                        ? (c * C_COSM - C_SINM * sqrtf(fmaxf(1.f - c * c, 0.f)))
                        : (c - C_MM);
        g_target[b] = tgt;
    }
}

// ---------------- kernel 2: persistent mma.sync GEMM + fused ArcNegFace epilogue ----------------
// 296 persistent CTAs pull tiles from an ordered atomic counter (same order as
// the old fixed grid: 4 m-tiles sharing a B tile stay adjacent -> L2 locality).
// Per tile: 128M x 128N, K=512 in 8 chunks of 64, 3-stage cp.async pipeline,
// kc fully unrolled; overlapped last n-tile (no OOB checks anywhere).
__global__ __launch_bounds__(256, 2)
void gemm_kernel(float* __restrict__ out)
{
    extern __shared__ char smem[];
    __shared__ int s_g;
    const uint32_t sbase = smem_u32(smem);
    const int tid  = threadIdx.x;
    const int wid  = tid >> 5;
    const int lane = tid & 31;
    const int wm   = (wid & 1) * 64;
    const int wn   = (wid >> 1) * 32;

    const char* Ag = (const char*)g_Ah;
    const char* Bg = (const char*)g_Bh;

    // per-thread constant pieces of the load addresses
    const int l_row = tid >> 3;           // 0..31 (row granule base)
    const int l_c   = tid & 7;            // 16B segment
    const uint32_t l_soff0 = (uint32_t)(l_row * 128 + ((l_c ^ (l_row & 7)) << 4));

    for (;;) {
        if (tid == 0) s_g = atomicAdd(&g_ctr, 1);
        __syncthreads();
        const int g = s_g;
        if (g >= NGEMM) break;
        const int m0 = (g & 3) * 128;     // 4 adjacent g share the B tile in L2
        int n0 = (g >> 2) * 128;
        if (n0 > NCLS - 128) n0 = NCLS - 128;   // overlapped last tile

        const size_t l_ga = (size_t)(m0 + l_row) * 512 + l_c * 8;
        const size_t l_gb = (size_t)(n0 + l_row) * 512 + l_c * 8;

        float acc[4][4][4];
#pragma unroll
        for (int mt = 0; mt < 4; mt++)
#pragma unroll
            for (int nt = 0; nt < 4; nt++)
#pragma unroll
                for (int i = 0; i < 4; i++) acc[mt][nt][i] = 0.f;

        auto load_chunk = [&](uint32_t sA, int kc) {
            const uint32_t sB = sA + 16384;
#pragma unroll
            for (int it = 0; it < 4; it++) {
                uint32_t soff = l_soff0 + (uint32_t)(32 * it * 128);
                cp_async16(sA + soff, Ag + (l_ga + (size_t)32 * it * 512 + kc * 64) * 2);
                cp_async16(sB + soff, Bg + (l_gb + (size_t)32 * it * 512 + kc * 64) * 2);
            }
            cp_commit();
        };

        load_chunk(sbase, 0);
        load_chunk(sbase + 32768, 1);

#pragma unroll
        for (int kc = 0; kc < 8; kc++) {
            const int stage = kc % 3;                       // compile-time
            const uint32_t sA = sbase + stage * 32768;      // immediate
            const uint32_t sB = sA + 16384;
            if (kc < 7) cp_wait<1>(); else cp_wait<0>();
            __syncthreads();
            if (kc + 2 < 8)
                load_chunk(sbase + ((kc + 2) % 3) * 32768, kc + 2);

#pragma unroll
            for (int ks = 0; ks < 4; ks++) {
                uint32_t a[4][4];
#pragma unroll
                for (int mt = 0; mt < 4; mt++) {
                    int row = wm + mt * 16 + (lane & 15);
                    int gr  = ks * 2 + (lane >> 4);
                    ldsm_x4(a[mt], sA + row * 128 + (((uint32_t)gr ^ (row & 7)) << 4));
                }
                uint32_t b[2][4];
#pragma unroll
                for (int p = 0; p < 2; p++) {
                    int nr = wn + p * 16 + (lane & 7) + ((lane >> 4) << 3);
                    int gr = ks * 2 + ((lane >> 3) & 1);
                    ldsm_x4(b[p], sB + nr * 128 + (((uint32_t)gr ^ (nr & 7)) << 4));
                }
#pragma unroll
                for (int mt = 0; mt < 4; mt++)
#pragma unroll
                    for (int nt = 0; nt < 4; nt++)
                        mma16816(acc[mt][nt], a[mt], b[nt >> 1][(nt & 1) * 2],
                                 b[nt >> 1][(nt & 1) * 2 + 1]);
            }
        }

        // ---- fused ArcNegFace epilogue (no bounds checks: n0+127 < NCLS) ----
#pragma unroll
        for (int mt = 0; mt < 4; mt++) {
            const int r0 = m0 + wm + mt * 16 + (lane >> 2);
            const int r1 = r0 + 8;
            const float tg0 = g_target[r0], tg1 = g_target[r1];
            const int lb0 = g_label[r0],  lb1 = g_label[r1];
            float* o0 = out + (size_t)r0 * NCLS;
            float* o1 = out + (size_t)r1 * NCLS;
#pragma unroll
            for (int nt = 0; nt < 4; nt++) {
                const int c0 = n0 + wn + nt * 8 + 2 * (lane & 3);
                float v[4];
#pragma unroll
                for (int i = 0; i < 4; i++) {
                    const float cs  = acc[mt][nt][i];
                    const float tg  = (i < 2) ? tg0 : tg1;
                    const int   lb  = (i < 2) ? lb0 : lb1;
                    const float dd  = cs - tg;
                    const float ts  = C_ALPHA * __expf(-0.5f * dd * dd);
                    float r = C_SCALE * (ts * cs + ts - 1.0f);
                    if (c0 + (i & 1) == lb) r = C_SCALE * tg;
                    v[i] = r;
                }
                *(float2*)(o0 + c0) = make_float2(v[0], v[1]);
                *(float2*)(o1 + c0) = make_float2(v[2], v[3]);
            }
        }
        __syncthreads();   // protect s_g before next steal
    }
}

// ---------------- launcher (2 launches, single stream) ----------------
extern "C" void kernel_launch(void* const* d_in, const int* in_sizes, int n_in,
                              void* d_out, int out_size)
{
    const float* x     = (const float*)d_in[0];
    const int*   lraw  = (const int*)d_in[1];
    const float* w     = (const float*)d_in[2];
    float*       out   = (float*)d_out;

    cudaFuncSetAttribute(gemm_kernel, cudaFuncAttributeMaxDynamicSharedMemorySize, 98304);

    prep_norm_kernel<<<NORMW_CTAS + BATCH / 8, 256>>>(w, x, lraw);
    gemm_kernel<<<PERSIST_CTAS, 256, 98304>>>(out);
}

// round 15
// speedup vs baseline: 1.1198x; 1.0059x over previous
#include <cuda_runtime.h>
#include <cuda_fp16.h>
#include <stdint.h>

#define DEVI static __device__ __forceinline__

#define BATCH 512
#define DIM   512
#define NCLS  100000
#define NTILES 782            // ceil(100000/128); last tile overlaps (n0 = 99872)

static constexpr float C_SCALE  = 64.0f;
static constexpr float C_ALPHA  = 1.2f;
static constexpr float C_COSM   =  0.87758256189037271612f;  // cos(0.5)
static constexpr float C_SINM   =  0.47942553860420300027f;  // sin(0.5)
static constexpr float C_THRESH = -0.87758256189037271612f;  // cos(pi-0.5)
static constexpr float C_MM     =  0.23971276930210150013f;  // sin(0.5)*0.5

// ---- SMEM layout (bytes) ----
#define SM_A0    0          // A stage 0 (fp16, 128x64, swizzled 128B rows)
#define SM_A1    16384
#define SM_BH0   32768      // B fp16 stage 0
#define SM_BH1   49152
#define SM_BF    65536      // B fp32 chunk (single buffer, 128x64 fp32)
#define SM_NORM  98304      // 128 floats: per-class inverse norms
#define SM_TOTAL 98816

// ---- device-global scratch (no allocation allowed) ----
__device__ __align__(1024) __half g_Ah[BATCH * DIM];
__device__ float g_target[BATCH];
__device__ int   g_label[BATCH];

// ---------------- PTX helpers ----------------
DEVI uint32_t smem_u32(const void* p) {
    uint32_t a;
    asm("{ .reg .u64 t; cvta.to.shared.u64 t, %1; cvt.u32.u64 %0, t; }" : "=r"(a) : "l"(p));
    return a;
}
DEVI void cp_async16(uint32_t dst, const void* src) {
    asm volatile("cp.async.cg.shared.global [%0], [%1], 16;" :: "r"(dst), "l"(src) : "memory");
}
DEVI void cp_commit() { asm volatile("cp.async.commit_group;" ::: "memory"); }
template <int N> DEVI void cp_wait() {
    asm volatile("cp.async.wait_group %0;" :: "n"(N) : "memory");
}
DEVI void ldsm_x4(uint32_t* r, uint32_t addr) {
    asm volatile("ldmatrix.sync.aligned.m8n8.x4.shared.b16 {%0,%1,%2,%3}, [%4];"
                 : "=r"(r[0]), "=r"(r[1]), "=r"(r[2]), "=r"(r[3]) : "r"(addr));
}
DEVI float4 lds_v4f32(uint32_t addr) {
    float4 f;
    asm volatile("ld.shared.v4.f32 {%0,%1,%2,%3}, [%4];"
                 : "=f"(f.x), "=f"(f.y), "=f"(f.z), "=f"(f.w) : "r"(addr));
    return f;
}
DEVI void sts_v2u32(uint32_t addr, uint32_t a, uint32_t b) {
    asm volatile("st.shared.v2.u32 [%0], {%1,%2};" :: "r"(addr), "r"(a), "r"(b) : "memory");
}
DEVI uint32_t pack_f16x2(float lo, float hi) {
    uint32_t d;
    asm("cvt.rn.f16x2.f32 %0, %1, %2;" : "=r"(d) : "f"(hi), "f"(lo));  // lo -> low half
    return d;
}
DEVI void mma16816(float* d, const uint32_t* a, uint32_t b0, uint32_t b1) {
    asm volatile(
        "mma.sync.aligned.m16n8k16.row.col.f32.f16.f16.f32 "
        "{%0,%1,%2,%3}, {%4,%5,%6,%7}, {%8,%9}, {%0,%1,%2,%3};"
        : "+f"(d[0]), "+f"(d[1]), "+f"(d[2]), "+f"(d[3])
        : "r"(a[0]), "r"(a[1]), "r"(a[2]), "r"(a[3]), "r"(b0), "r"(b1));
}

// ---------------- kernel 1: prep (label fix + norm_x + exact fp32 target) ----------------
__global__ void prep_kernel(const float* __restrict__ x,
                            const int* __restrict__ lraw,
                            const float* __restrict__ w)
{
    __shared__ int s_or;
    const int tid  = threadIdx.x;
    const int wid  = tid >> 5;
    const int lane = tid & 31;
    const int b    = blockIdx.x * 8 + wid;

    if (tid == 0) s_or = 0;
    __syncthreads();
    if (tid < 256) {
        if (lraw[2 * tid + 1] != 0) atomicOr(&s_or, 1);
    }
    __syncthreads();
    const int lb = s_or ? lraw[b] : lraw[2 * b];   // int32 vs int64 low word
    if (lane == 0) g_label[b] = lb;

    const float4* xp = (const float4*)(x + (size_t)b * DIM);
    const float4* wp = (const float4*)(w + (size_t)lb * DIM);
    float4 v[4];
    float xx = 0.f, ww = 0.f, xw = 0.f;
#pragma unroll
    for (int i = 0; i < 4; i++) {
        v[i] = xp[lane + 32 * i];
        float4 c = wp[lane + 32 * i];
        xx += v[i].x * v[i].x + v[i].y * v[i].y + v[i].z * v[i].z + v[i].w * v[i].w;
        ww += c.x * c.x + c.y * c.y + c.z * c.z + c.w * c.w;
        xw += v[i].x * c.x + v[i].y * c.y + v[i].z * c.z + v[i].w * c.w;
    }
#pragma unroll
    for (int o = 16; o > 0; o >>= 1) {
        xx += __shfl_xor_sync(0xFFFFFFFFu, xx, o);
        ww += __shfl_xor_sync(0xFFFFFFFFu, ww, o);
        xw += __shfl_xor_sync(0xFFFFFFFFu, xw, o);
    }

    float rx = rsqrtf(xx);
    rx = rx * (1.5f - 0.5f * xx * rx * rx);   // NR refine
    uint2* dp = (uint2*)(g_Ah + (size_t)b * DIM);
#pragma unroll
    for (int i = 0; i < 4; i++) {
        __half h0 = __float2half_rn(v[i].x * rx);
        __half h1 = __float2half_rn(v[i].y * rx);
        __half h2 = __float2half_rn(v[i].z * rx);
        __half h3 = __float2half_rn(v[i].w * rx);
        __half2 p01 = __halves2half2(h0, h1);
        __half2 p23 = __halves2half2(h2, h3);
        uint2 u;
        u.x = *(uint32_t*)&p01;
        u.y = *(uint32_t*)&p23;
        dp[lane + 32 * i] = u;
    }

    if (lane == 0) {
        float p = xx * ww;
        float r = rsqrtf(p);
        r = r * (1.5f - 0.5f * p * r * r);
        float c = xw * r;
        float tgt = (c > C_THRESH)
                        ? (c * C_COSM - C_SINM * sqrtf(fmaxf(1.f - c * c, 0.f)))
                        : (c - C_MM);
        g_target[b] = tgt;
    }
}

// ---------------- kernel 2: GEMM with in-pipeline fp32->fp16 B conversion ----------------
// CTA tile 128M x 128N, K=512 in 8 chunks of 64.
// Per chunk: cp.async A fp16 (double-buffered) + raw fp32 B (single buffer);
// block-wide vectorized convert fp32->fp16 into Bh stage (accumulating per-class
// sumsq in registers); then the validated ldsm+mma mainloop on fp16 tiles.
// Epilogue scales cos by rsqrt(sumsq[col]) (exact fp32), diag = exact target.
__global__ __launch_bounds__(256, 2)
void gemm_kernel(const float* __restrict__ w, float* __restrict__ out)
{
    extern __shared__ char smem[];
    const uint32_t sbase = smem_u32(smem);
    const int tid  = threadIdx.x;
    const int wid  = tid >> 5;
    const int lane = tid & 31;
    const int m0   = blockIdx.x * 128;   // 4 m-tiles fastest -> share B tile in L2
    int n0 = blockIdx.y * 128;
    if (n0 > NCLS - 128) n0 = NCLS - 128;   // overlapped last tile, no OOB anywhere
    const int wm   = (wid & 1) * 64;
    const int wn   = (wid >> 1) * 32;

    const char* Ag = (const char*)g_Ah;

    float acc[4][4][4];
#pragma unroll
    for (int mt = 0; mt < 4; mt++)
#pragma unroll
        for (int nt = 0; nt < 4; nt++)
#pragma unroll
            for (int i = 0; i < 4; i++) acc[mt][nt][i] = 0.f;

    float sq[8];   // per-thread partial sumsq for rows b_res + 16*it
#pragma unroll
    for (int i = 0; i < 8; i++) sq[i] = 0.f;

    // ---- A loader constants (fp16, as in the 180us kernel) ----
    const int aw_row = tid >> 3;          // 0..31
    const int aw_c   = tid & 7;
    const uint32_t a_soff0 = (uint32_t)(aw_row * 128 + ((aw_c ^ (aw_row & 7)) << 4));
    const size_t a_ga = (size_t)(m0 + aw_row) * 512 + aw_c * 8;

    // ---- B fp32 loader / converter constants ----
    // thread owns granule column g = tid&15 (4 fp32) of rows b_res + 16*it.
    const int b_res = tid >> 4;           // 0..15
    const int b_g   = tid & 15;
    const uint32_t b_swz   = (uint32_t)((b_g ^ b_res) << 4);       // (row&15)==b_res
    const uint32_t b_sbase = (uint32_t)(b_res * 256) + b_swz;      // + 4096*it
    // Bh store: col base = 4*b_g halves = 8*b_g bytes: granule b_g>>1, half (b_g&1)*8
    const uint32_t bh_gr   = (uint32_t)(b_g >> 1);
    const uint32_t bh_half = (uint32_t)((b_g & 1) * 8);

    auto load_chunk = [&](uint32_t sA, int kc) {
#pragma unroll
        for (int it = 0; it < 4; it++) {
            uint32_t soff = a_soff0 + (uint32_t)(32 * it * 128);
            cp_async16(sA + soff, Ag + (a_ga + (size_t)(32 * it) * 512 + kc * 64) * 2);
        }
        const float* wsrc = w + (size_t)(n0 + b_res) * 512 + kc * 64 + b_g * 4;
#pragma unroll
        for (int it = 0; it < 8; it++) {
            cp_async16(sbase + SM_BF + b_sbase + (uint32_t)(4096 * it),
                       (const void*)(wsrc + (size_t)(16 * it) * 512));
        }
        cp_commit();
    };

    load_chunk(sbase + SM_A0, 0);

#pragma unroll
    for (int kc = 0; kc < 8; kc++) {
        const uint32_t sA  = sbase + ((kc & 1) ? SM_A1 : SM_A0);
        const uint32_t sBH = sbase + ((kc & 1) ? SM_BH1 : SM_BH0);
        cp_wait<0>();
        __syncthreads();                    // A + Bf32 ready

        // ---- convert this chunk's B fp32 -> fp16 (+ sumsq) ----
#pragma unroll
        for (int it = 0; it < 8; it++) {
            const int row = b_res + 16 * it;
            float4 f = lds_v4f32(sbase + SM_BF + b_sbase + (uint32_t)(4096 * it));
            sq[it] = fmaf(f.x, f.x, fmaf(f.y, f.y,
                      fmaf(f.z, f.z, fmaf(f.w, f.w, sq[it]))));
            uint32_t u0 = pack_f16x2(f.x, f.y);
            uint32_t u1 = pack_f16x2(f.z, f.w);
            sts_v2u32(sBH + (uint32_t)(row * 128)
                          + ((bh_gr ^ (uint32_t)(row & 7)) << 4) + bh_half, u0, u1);
        }
        __syncthreads();                    // Bh visible; Bf32 free for reuse

        if (kc < 7)
            load_chunk(sbase + ((kc & 1) ? SM_A0 : SM_A1), kc + 1);

        // ---- validated ldsm + mma mainloop (fp16, identical to 180us kernel) ----
#pragma unroll
        for (int ks = 0; ks < 4; ks++) {
            uint32_t a[4][4];
#pragma unroll
            for (int mt = 0; mt < 4; mt++) {
                int row = wm + mt * 16 + (lane & 15);
                int gr  = ks * 2 + (lane >> 4);
                ldsm_x4(a[mt], sA + row * 128 + (((uint32_t)gr ^ (row & 7)) << 4));
            }
            uint32_t b[2][4];
#pragma unroll
            for (int p = 0; p < 2; p++) {
                int nr = wn + p * 16 + (lane & 7) + ((lane >> 4) << 3);
                int gr = ks * 2 + ((lane >> 3) & 1);
                ldsm_x4(b[p], sBH + nr * 128 + (((uint32_t)gr ^ (nr & 7)) << 4));
            }
#pragma unroll
            for (int mt = 0; mt < 4; mt++)
#pragma unroll
                for (int nt = 0; nt < 4; nt++)
                    mma16816(acc[mt][nt], a[mt], b[nt >> 1][(nt & 1) * 2],
                             b[nt >> 1][(nt & 1) * 2 + 1]);
        }
    }

    // ---- finalize per-class inverse norms ----
    // row r = b_res + 16*it; 16 threads (b_g) hold partials -> half-warp reduce.
#pragma unroll
    for (int it = 0; it < 8; it++) {
        float s = sq[it];
        s += __shfl_xor_sync(0xFFFFFFFFu, s, 1);
        s += __shfl_xor_sync(0xFFFFFFFFu, s, 2);
        s += __shfl_xor_sync(0xFFFFFFFFu, s, 4);
        s += __shfl_xor_sync(0xFFFFFFFFu, s, 8);
        if (b_g == 0) {
            float r = rsqrtf(s);
            r = r * (1.5f - 0.5f * s * r * r);
            *(float*)(smem + SM_NORM + (b_res + 16 * it) * 4) = r;
        }
    }
    __syncthreads();

    // ---- fused ArcNegFace epilogue with per-column norm scale ----
#pragma unroll
    for (int mt = 0; mt < 4; mt++) {
        const int r0 = m0 + wm + mt * 16 + (lane >> 2);
        const int r1 = r0 + 8;
        const float tg0 = g_target[r0], tg1 = g_target[r1];
        const int lb0 = g_label[r0],  lb1 = g_label[r1];
        float* o0 = out + (size_t)r0 * NCLS;
        float* o1 = out + (size_t)r1 * NCLS;
#pragma unroll
        for (int nt = 0; nt < 4; nt++) {
            const int ct = wn + nt * 8 + 2 * (lane & 3);   // col within tile (even)
            const int c0 = n0 + ct;
            const float2 nv = *(const float2*)(smem + SM_NORM + ct * 4);
            float v[4];
#pragma unroll
            for (int i = 0; i < 4; i++) {
                const float cs  = acc[mt][nt][i] * ((i & 1) ? nv.y : nv.x);
                const float tg  = (i < 2) ? tg0 : tg1;
                const int   lb  = (i < 2) ? lb0 : lb1;
                const float dd  = cs - tg;
                const float ts  = C_ALPHA * __expf(-0.5f * dd * dd);
                float r = C_SCALE * (ts * cs + ts - 1.0f);
                if (c0 + (i & 1) == lb) r = C_SCALE * tg;
                v[i] = r;
            }
            *(float2*)(o0 + c0) = make_float2(v[0], v[1]);
            *(float2*)(o1 + c0) = make_float2(v[2], v[3]);
        }
    }
}

// ---------------- launcher (2 launches, single stream) ----------------
extern "C" void kernel_launch(void* const* d_in, const int* in_sizes, int n_in,
                              void* d_out, int out_size)
{
    const float* x     = (const float*)d_in[0];
    const int*   lraw  = (const int*)d_in[1];
    const float* w     = (const float*)d_in[2];
    float*       out   = (float*)d_out;

    cudaFuncSetAttribute(gemm_kernel, cudaFuncAttributeMaxDynamicSharedMemorySize, SM_TOTAL);

    prep_kernel<<<BATCH / 8, 256>>>(x, lraw, w);

    dim3 grid(4, NTILES);
    gemm_kernel<<<grid, 256, SM_TOTAL>>>(w, out);
}

// round 16
// speedup vs baseline: 1.2904x; 1.1524x over previous
#include <cuda_runtime.h>
#include <cuda_fp16.h>
#include <stdint.h>

#define DEVI static __device__ __forceinline__

#define BATCH 512
#define DIM   512
#define NCLS  100000
#define NTILES 782            // ceil(100000/128); last tile overlaps (n0 = 99872)
#define NORMW_CTAS 12500      // NCLS/8 rows per CTA (8 warps x 1 row)

static constexpr float C_SCALE  = 64.0f;
static constexpr float C_ALPHA  = 1.2f;
static constexpr float C_COSM   =  0.87758256189037271612f;  // cos(0.5)
static constexpr float C_SINM   =  0.47942553860420300027f;  // sin(0.5)
static constexpr float C_THRESH = -0.87758256189037271612f;  // cos(pi-0.5)
static constexpr float C_MM     =  0.23971276930210150013f;  // sin(0.5)*0.5

// ---- device-global scratch (no allocation allowed) ----
__device__ __align__(1024) __half g_Ah[BATCH * DIM];
__device__ __align__(1024) __half g_Bh[(size_t)NCLS * DIM];
__device__ float g_target[BATCH];
__device__ int   g_label[BATCH];

// ---------------- PTX helpers ----------------
DEVI uint32_t smem_u32(const void* p) {
    uint32_t a;
    asm("{ .reg .u64 t; cvta.to.shared.u64 t, %1; cvt.u32.u64 %0, t; }" : "=r"(a) : "l"(p));
    return a;
}
DEVI void cp_async16(uint32_t dst, const void* src) {
    asm volatile("cp.async.cg.shared.global [%0], [%1], 16;" :: "r"(dst), "l"(src) : "memory");
}
DEVI void cp_commit() { asm volatile("cp.async.commit_group;" ::: "memory"); }
template <int N> DEVI void cp_wait() {
    asm volatile("cp.async.wait_group %0;" :: "n"(N) : "memory");
}
DEVI void ldsm_x4(uint32_t* r, uint32_t addr) {
    asm volatile("ldmatrix.sync.aligned.m8n8.x4.shared.b16 {%0,%1,%2,%3}, [%4];"
                 : "=r"(r[0]), "=r"(r[1]), "=r"(r[2]), "=r"(r[3]) : "r"(addr));
}
DEVI void mma16816(float* d, const uint32_t* a, uint32_t b0, uint32_t b1) {
    asm volatile(
        "mma.sync.aligned.m16n8k16.row.col.f32.f16.f16.f32 "
        "{%0,%1,%2,%3}, {%4,%5,%6,%7}, {%8,%9}, {%0,%1,%2,%3};"
        : "+f"(d[0]), "+f"(d[1]), "+f"(d[2]), "+f"(d[3])
        : "r"(a[0]), "r"(a[1]), "r"(a[2]), "r"(a[3]), "r"(b0), "r"(b1));
}
DEVI void norm_row_store(const float4* sp, __half* dst, int lane) {
    float4 v[4];
    float ss = 0.f;
#pragma unroll
    for (int i = 0; i < 4; i++) {
        v[i] = sp[lane + 32 * i];
        ss += v[i].x * v[i].x + v[i].y * v[i].y + v[i].z * v[i].z + v[i].w * v[i].w;
    }
#pragma unroll
    for (int o = 16; o > 0; o >>= 1) ss += __shfl_xor_sync(0xFFFFFFFFu, ss, o);
    float r = rsqrtf(ss);
    r = r * (1.5f - 0.5f * ss * r * r);   // NR refine -> ~fp32 exact
    uint2* dp = (uint2*)dst;
#pragma unroll
    for (int i = 0; i < 4; i++) {
        __half h0 = __float2half_rn(v[i].x * r);
        __half h1 = __float2half_rn(v[i].y * r);
        __half h2 = __float2half_rn(v[i].z * r);
        __half h3 = __float2half_rn(v[i].w * r);
        __half2 p01 = __halves2half2(h0, h1);
        __half2 p23 = __halves2half2(h2, h3);
        uint2 u;
        u.x = *(uint32_t*)&p01;
        u.y = *(uint32_t*)&p23;
        dp[lane + 32 * i] = u;
    }
}

// ---------------- kernel 1: norm_w (blocks 0..12499) + prep (blocks 12500..12563) ----------------
__global__ void prep_norm_kernel(const float* __restrict__ w,
                                 const float* __restrict__ x,
                                 const int* __restrict__ lraw)
{
    const int tid  = threadIdx.x;
    const int wid  = tid >> 5;
    const int lane = tid & 31;

    if (blockIdx.x < NORMW_CTAS) {
        const int row = blockIdx.x * 8 + wid;
        if (row < NCLS)
            norm_row_store((const float4*)(w + (size_t)row * DIM),
                           g_Bh + (size_t)row * DIM, lane);
        return;
    }

    // ---- prep path: label fix + norm_x + exact fp32 target ----
    __shared__ int s_or;
    const int b = (blockIdx.x - NORMW_CTAS) * 8 + wid;

    if (tid == 0) s_or = 0;
    __syncthreads();
    if (tid < 256) {
        if (lraw[2 * tid + 1] != 0) atomicOr(&s_or, 1);
    }
    __syncthreads();
    const int lb = s_or ? lraw[b] : lraw[2 * b];   // int32 vs int64 low word
    if (lane == 0) g_label[b] = lb;

    const float4* xp = (const float4*)(x + (size_t)b * DIM);
    const float4* wp = (const float4*)(w + (size_t)lb * DIM);
    float4 v[4];
    float xx = 0.f, ww = 0.f, xw = 0.f;
#pragma unroll
    for (int i = 0; i < 4; i++) {
        v[i] = xp[lane + 32 * i];
        float4 c = wp[lane + 32 * i];
        xx += v[i].x * v[i].x + v[i].y * v[i].y + v[i].z * v[i].z + v[i].w * v[i].w;
        ww += c.x * c.x + c.y * c.y + c.z * c.z + c.w * c.w;
        xw += v[i].x * c.x + v[i].y * c.y + v[i].z * c.z + v[i].w * c.w;
    }
#pragma unroll
    for (int o = 16; o > 0; o >>= 1) {
        xx += __shfl_xor_sync(0xFFFFFFFFu, xx, o);
        ww += __shfl_xor_sync(0xFFFFFFFFu, ww, o);
        xw += __shfl_xor_sync(0xFFFFFFFFu, xw, o);
    }

    float rx = rsqrtf(xx);
    rx = rx * (1.5f - 0.5f * xx * rx * rx);
    uint2* dp = (uint2*)(g_Ah + (size_t)b * DIM);
#pragma unroll
    for (int i = 0; i < 4; i++) {
        __half h0 = __float2half_rn(v[i].x * rx);
        __half h1 = __float2half_rn(v[i].y * rx);
        __half h2 = __float2half_rn(v[i].z * rx);
        __half h3 = __float2half_rn(v[i].w * rx);
        __half2 p01 = __halves2half2(h0, h1);
        __half2 p23 = __halves2half2(h2, h3);
        uint2 u;
        u.x = *(uint32_t*)&p01;
        u.y = *(uint32_t*)&p23;
        dp[lane + 32 * i] = u;
    }

    if (lane == 0) {
        float p = xx * ww;
        float r = rsqrtf(p);
        r = r * (1.5f - 0.5f * p * r * r);
        float c = xw * r;
        float tgt = (c > C_THRESH)
                        ? (c * C_COSM - C_SINM * sqrtf(fmaxf(1.f - c * c, 0.f)))
                        : (c - C_MM);
        g_target[b] = tgt;
    }
}

// ---------------- kernel 2: mma.sync GEMM, 4 warps @ 64x64 warp tile ----------------
// CTA tile 128M x 128N with 4 warps (2m x 2n of 64x64) -> ldsm duplication drops
// from (4,2) to (2,2): 96KB crossbar/chunk vs 128KB, same tensor work.
// K=512 in 8 chunks of 64, 3-stage cp.async, kc fully unrolled.
// Overlapped last n-tile (no OOB checks). Fragment formulas identical to the
// verified 8-warp kernel; only p/nt ranges extend.
__global__ __launch_bounds__(128, 2)
void gemm_kernel(float* __restrict__ out)
{
    extern __shared__ char smem[];
    const uint32_t sbase = smem_u32(smem);
    const int tid  = threadIdx.x;
    const int wid  = tid >> 5;          // 0..3
    const int lane = tid & 31;
    const int m0   = blockIdx.x * 128;  // 4 m-tiles fastest -> share B tile in L2
    int n0 = blockIdx.y * 128;
    if (n0 > NCLS - 128) n0 = NCLS - 128;   // overlapped last tile, no OOB anywhere
    const int wm   = (wid & 1) * 64;
    const int wn   = (wid >> 1) * 64;

    const char* Ag = (const char*)g_Ah;
    const char* Bg = (const char*)g_Bh;

    float acc[4][8][4];
#pragma unroll
    for (int mt = 0; mt < 4; mt++)
#pragma unroll
        for (int nt = 0; nt < 8; nt++)
#pragma unroll
            for (int i = 0; i < 4; i++) acc[mt][nt][i] = 0.f;

    // per-thread constant pieces of the load addresses (128 threads)
    const int l_row = tid >> 3;           // 0..15 (row granule base)
    const int l_c   = tid & 7;            // 16B segment
    const uint32_t l_soff0 = (uint32_t)(l_row * 128 + ((l_c ^ (l_row & 7)) << 4));
    const size_t l_ga = (size_t)(m0 + l_row) * 512 + l_c * 8;
    const size_t l_gb = (size_t)(n0 + l_row) * 512 + l_c * 8;

    auto load_chunk = [&](uint32_t sA, int kc) {
        const uint32_t sB = sA + 16384;
#pragma unroll
        for (int it = 0; it < 8; it++) {
            uint32_t soff = l_soff0 + (uint32_t)(16 * it * 128);
            cp_async16(sA + soff, Ag + (l_ga + (size_t)16 * it * 512 + kc * 64) * 2);
            cp_async16(sB + soff, Bg + (l_gb + (size_t)16 * it * 512 + kc * 64) * 2);
        }
        cp_commit();
    };

    load_chunk(sbase, 0);
    load_chunk(sbase + 32768, 1);

#pragma unroll
    for (int kc = 0; kc < 8; kc++) {
        const int stage = kc % 3;                       // compile-time
        const uint32_t sA = sbase + stage * 32768;      // immediate
        const uint32_t sB = sA + 16384;
        if (kc < 7) cp_wait<1>(); else cp_wait<0>();
        __syncthreads();
        if (kc + 2 < 8)
            load_chunk(sbase + ((kc + 2) % 3) * 32768, kc + 2);

#pragma unroll
        for (int ks = 0; ks < 4; ks++) {
            uint32_t a[4][4];
#pragma unroll
            for (int mt = 0; mt < 4; mt++) {
                int row = wm + mt * 16 + (lane & 15);
                int gr  = ks * 2 + (lane >> 4);
                ldsm_x4(a[mt], sA + row * 128 + (((uint32_t)gr ^ (row & 7)) << 4));
            }
            uint32_t b[4][4];
#pragma unroll
            for (int p = 0; p < 4; p++) {
                int nr = wn + p * 16 + (lane & 7) + ((lane >> 4) << 3);
                int gr = ks * 2 + ((lane >> 3) & 1);
                ldsm_x4(b[p], sB + nr * 128 + (((uint32_t)gr ^ (nr & 7)) << 4));
            }
#pragma unroll
            for (int mt = 0; mt < 4; mt++)
#pragma unroll
                for (int nt = 0; nt < 8; nt++)
                    mma16816(acc[mt][nt], a[mt], b[nt >> 1][(nt & 1) * 2],
                             b[nt >> 1][(nt & 1) * 2 + 1]);
        }
    }

    // ---- fused ArcNegFace epilogue (no bounds checks: n0+127 < NCLS) ----
#pragma unroll
    for (int mt = 0; mt < 4; mt++) {
        const int r0 = m0 + wm + mt * 16 + (lane >> 2);
        const int r1 = r0 + 8;
        const float tg0 = g_target[r0], tg1 = g_target[r1];
        const int lb0 = g_label[r0],  lb1 = g_label[r1];
        float* o0 = out + (size_t)r0 * NCLS;
        float* o1 = out + (size_t)r1 * NCLS;
#pragma unroll
        for (int nt = 0; nt < 8; nt++) {
            const int c0 = n0 + wn + nt * 8 + 2 * (lane & 3);
            float v[4];
#pragma unroll
            for (int i = 0; i < 4; i++) {
                const float cs  = acc[mt][nt][i];
                const float tg  = (i < 2) ? tg0 : tg1;
                const int   lb  = (i < 2) ? lb0 : lb1;
                const float dd  = cs - tg;
                const float ts  = C_ALPHA * __expf(-0.5f * dd * dd);
                float r = C_SCALE * (ts * cs + ts - 1.0f);
                if (c0 + (i & 1) == lb) r = C_SCALE * tg;
                v[i] = r;
            }
            *(float2*)(o0 + c0) = make_float2(v[0], v[1]);
            *(float2*)(o1 + c0) = make_float2(v[2], v[3]);
        }
    }
}

// ---------------- launcher (2 launches, single stream) ----------------
extern "C" void kernel_launch(void* const* d_in, const int* in_sizes, int n_in,
                              void* d_out, int out_size)
{
    const float* x     = (const float*)d_in[0];
    const int*   lraw  = (const int*)d_in[1];
    const float* w     = (const float*)d_in[2];
    float*       out   = (float*)d_out;

    cudaFuncSetAttribute(gemm_kernel, cudaFuncAttributeMaxDynamicSharedMemorySize, 98304);

    prep_norm_kernel<<<NORMW_CTAS + BATCH / 8, 256>>>(w, x, lraw);

    dim3 grid(4, NTILES);
    gemm_kernel<<<grid, 128, 98304>>>(out);
}

// round 17
// speedup vs baseline: 1.2938x; 1.0026x over previous
#include <cuda_runtime.h>
#include <cuda_fp16.h>
#include <stdint.h>

#define DEVI static __device__ __forceinline__

#define BATCH 512
#define DIM   512
#define NCLS  100000
#define NTILES 782            // ceil(100000/128); last tile overlaps (n0 = 99872)
#define PRE_TILES 74          // tiles pre-normalized by prep (one wave's worth)
#define PRE_ROWS (PRE_TILES * 128)   // 9472
#define PRENORM_CTAS (PRE_ROWS / 8)  // 1184

static constexpr float C_SCALE  = 64.0f;
static constexpr float C_ALPHA  = 1.2f;
static constexpr float C_COSM   =  0.87758256189037271612f;  // cos(0.5)
static constexpr float C_SINM   =  0.47942553860420300027f;  // sin(0.5)
static constexpr float C_THRESH = -0.87758256189037271612f;  // cos(pi-0.5)
static constexpr float C_MM     =  0.23971276930210150013f;  // sin(0.5)*0.5

// ---- device-global scratch (no allocation allowed) ----
__device__ __align__(1024) __half g_Ah[BATCH * DIM];
__device__ __align__(1024) __half g_Bh[(size_t)NCLS * DIM];
__device__ float g_target[BATCH];
__device__ int   g_label[BATCH];
__device__ volatile int g_flag[NTILES];

// ---------------- PTX helpers ----------------
DEVI uint32_t smem_u32(const void* p) {
    uint32_t a;
    asm("{ .reg .u64 t; cvta.to.shared.u64 t, %1; cvt.u32.u64 %0, t; }" : "=r"(a) : "l"(p));
    return a;
}
DEVI void cp_async16(uint32_t dst, const void* src) {
    asm volatile("cp.async.cg.shared.global [%0], [%1], 16;" :: "r"(dst), "l"(src) : "memory");
}
DEVI void cp_commit() { asm volatile("cp.async.commit_group;" ::: "memory"); }
template <int N> DEVI void cp_wait() {
    asm volatile("cp.async.wait_group %0;" :: "n"(N) : "memory");
}
DEVI void prefetch_l2(const void* p) {
    asm volatile("prefetch.global.L2 [%0];" :: "l"(p));
}
DEVI void ldsm_x4(uint32_t* r, uint32_t addr) {
    asm volatile("ldmatrix.sync.aligned.m8n8.x4.shared.b16 {%0,%1,%2,%3}, [%4];"
                 : "=r"(r[0]), "=r"(r[1]), "=r"(r[2]), "=r"(r[3]) : "r"(addr));
}
DEVI void mma16816(float* d, const uint32_t* a, uint32_t b0, uint32_t b1) {
    asm volatile(
        "mma.sync.aligned.m16n8k16.row.col.f32.f16.f16.f32 "
        "{%0,%1,%2,%3}, {%4,%5,%6,%7}, {%8,%9}, {%0,%1,%2,%3};"
        : "+f"(d[0]), "+f"(d[1]), "+f"(d[2]), "+f"(d[3])
        : "r"(a[0]), "r"(a[1]), "r"(a[2]), "r"(a[3]), "r"(b0), "r"(b1));
}
DEVI void norm_row_store(const float4* sp, __half* dst, int lane) {
    float4 v[4];
    float ss = 0.f;
#pragma unroll
    for (int i = 0; i < 4; i++) {
        v[i] = sp[lane + 32 * i];
        ss += v[i].x * v[i].x + v[i].y * v[i].y + v[i].z * v[i].z + v[i].w * v[i].w;
    }
#pragma unroll
    for (int o = 16; o > 0; o >>= 1) ss += __shfl_xor_sync(0xFFFFFFFFu, ss, o);
    float r = rsqrtf(ss);
    r = r * (1.5f - 0.5f * ss * r * r);   // NR refine -> ~fp32 exact
    uint2* dp = (uint2*)dst;
#pragma unroll
    for (int i = 0; i < 4; i++) {
        __half h0 = __float2half_rn(v[i].x * r);
        __half h1 = __float2half_rn(v[i].y * r);
        __half h2 = __float2half_rn(v[i].z * r);
        __half h3 = __float2half_rn(v[i].w * r);
        __half2 p01 = __halves2half2(h0, h1);
        __half2 p23 = __halves2half2(h2, h3);
        uint2 u;
        u.x = *(uint32_t*)&p01;
        u.y = *(uint32_t*)&p23;
        dp[lane + 32 * i] = u;
    }
}

// ---------------- kernel 1: prep ----------------
// blocks [0, PRENORM_CTAS): normalize w rows 0..PRE_ROWS (tiles 0..73) + init flags
// blocks [PRENORM_CTAS, +64): label fix + norm_x + exact fp32 target
__global__ void prep_kernel(const float* __restrict__ w,
                            const float* __restrict__ x,
                            const int* __restrict__ lraw)
{
    const int tid  = threadIdx.x;
    const int wid  = tid >> 5;
    const int lane = tid & 31;

    if (blockIdx.x < PRENORM_CTAS) {
        // flag init (first few blocks cover all 782)
        int idx = blockIdx.x * 256 + tid;
        if (idx < NTILES) g_flag[idx] = (idx < PRE_TILES) ? 4 : 0;
        const int row = blockIdx.x * 8 + wid;
        norm_row_store((const float4*)(w + (size_t)row * DIM),
                       g_Bh + (size_t)row * DIM, lane);
        return;
    }

    __shared__ int s_or;
    const int b = (blockIdx.x - PRENORM_CTAS) * 8 + wid;

    if (tid == 0) s_or = 0;
    __syncthreads();
    if (tid < 256) {
        if (lraw[2 * tid + 1] != 0) atomicOr(&s_or, 1);
    }
    __syncthreads();
    const int lb = s_or ? lraw[b] : lraw[2 * b];   // int32 vs int64 low word
    if (lane == 0) g_label[b] = lb;

    const float4* xp = (const float4*)(x + (size_t)b * DIM);
    const float4* wp = (const float4*)(w + (size_t)lb * DIM);
    float4 v[4];
    float xx = 0.f, ww = 0.f, xw = 0.f;
#pragma unroll
    for (int i = 0; i < 4; i++) {
        v[i] = xp[lane + 32 * i];
        float4 c = wp[lane + 32 * i];
        xx += v[i].x * v[i].x + v[i].y * v[i].y + v[i].z * v[i].z + v[i].w * v[i].w;
        ww += c.x * c.x + c.y * c.y + c.z * c.z + c.w * c.w;
        xw += v[i].x * c.x + v[i].y * c.y + v[i].z * c.z + v[i].w * c.w;
    }
#pragma unroll
    for (int o = 16; o > 0; o >>= 1) {
        xx += __shfl_xor_sync(0xFFFFFFFFu, xx, o);
        ww += __shfl_xor_sync(0xFFFFFFFFu, ww, o);
        xw += __shfl_xor_sync(0xFFFFFFFFu, xw, o);
    }

    float rx = rsqrtf(xx);
    rx = rx * (1.5f - 0.5f * xx * rx * rx);
    uint2* dp = (uint2*)(g_Ah + (size_t)b * DIM);
#pragma unroll
    for (int i = 0; i < 4; i++) {
        __half h0 = __float2half_rn(v[i].x * rx);
        __half h1 = __float2half_rn(v[i].y * rx);
        __half h2 = __float2half_rn(v[i].z * rx);
        __half h3 = __float2half_rn(v[i].w * rx);
        __half2 p01 = __halves2half2(h0, h1);
        __half2 p23 = __halves2half2(h2, h3);
        uint2 u;
        u.x = *(uint32_t*)&p01;
        u.y = *(uint32_t*)&p23;
        dp[lane + 32 * i] = u;
    }

    if (lane == 0) {
        float p = xx * ww;
        float r = rsqrtf(p);
        r = r * (1.5f - 0.5f * p * r * r);
        float c = xw * r;
        float tgt = (c > C_THRESH)
                        ? (c * C_COSM - C_SINM * sqrtf(fmaxf(1.f - c * c, 0.f)))
                        : (c - C_MM);
        g_target[b] = tgt;
    }
}

// ---------------- kernel 2: GEMM with pipelined next-wave B production ----------------
// CTA (bx=blockIdx.x, by=blockIdx.y), linear bid = 4*by+bx.
//  start: L2-prefetch raw w rows of tile by+74 quarter bx; spin on flag(s) of
//         its own B tile (set one wave earlier by same-SM-slot CTAs).
//  mainloop/epilogue: byte-identical to the verified 180us kernel.
//  end: normalize 32 rows of tile by+74 (accumulators dead -> regs free),
//       fence, atomicAdd flag.
__global__ __launch_bounds__(256, 2)
void gemm_kernel(const float* __restrict__ w, float* __restrict__ out)
{
    extern __shared__ char smem[];
    const uint32_t sbase = smem_u32(smem);
    const int tid  = threadIdx.x;
    const int wid  = tid >> 5;
    const int lane = tid & 31;
    const int m0   = blockIdx.x * 128;   // 4 m-tiles fastest -> share B tile in L2
    const int by   = blockIdx.y;
    int n0 = by * 128;
    if (n0 > NCLS - 128) n0 = NCLS - 128;   // overlapped last tile, no OOB anywhere
    const int wm   = (wid & 1) * 64;
    const int wn   = (wid >> 1) * 32;

    // production assignment: tile tp, quarter q = blockIdx.x
    const int tp = by + PRE_TILES;               // may be >= NTILES (no production)
    const int prow0 = tp * 128 + blockIdx.x * 32;

    // ---- L2 prefetch of production source rows (fire-and-forget) ----
    if (tp < NTILES) {
        const int pr = prow0 + (tid >> 3);       // 32 rows, 8 threads each
        if (pr < NCLS) {
            const float* src = w + (size_t)pr * 512 + (tid & 7) * 64;
            prefetch_l2(src);
            prefetch_l2(src + 32);
        }
    }

    // ---- wait for this CTA's B tile(s) ----
    if (tid == 0) {
        const int t0 = n0 >> 7;
        const int t1 = (n0 + 127) >> 7;
        while (g_flag[t0] < 4) __nanosleep(32);
        while (g_flag[t1] < 4) __nanosleep(32);
    }
    __syncthreads();
    __threadfence();

    const char* Ag = (const char*)g_Ah;
    const char* Bg = (const char*)g_Bh;

    float acc[4][4][4];
#pragma unroll
    for (int mt = 0; mt < 4; mt++)
#pragma unroll
        for (int nt = 0; nt < 4; nt++)
#pragma unroll
            for (int i = 0; i < 4; i++) acc[mt][nt][i] = 0.f;

    // per-thread constant pieces of the load addresses
    const int l_row = tid >> 3;           // 0..31 (row granule base)
    const int l_c   = tid & 7;            // 16B segment
    const uint32_t l_soff0 = (uint32_t)(l_row * 128 + ((l_c ^ (l_row & 7)) << 4));
    const size_t l_ga = (size_t)(m0 + l_row) * 512 + l_c * 8;
    const size_t l_gb = (size_t)(n0 + l_row) * 512 + l_c * 8;

    auto load_chunk = [&](uint32_t sA, int kc) {
        const uint32_t sB = sA + 16384;
#pragma unroll
        for (int it = 0; it < 4; it++) {
            uint32_t soff = l_soff0 + (uint32_t)(32 * it * 128);
            cp_async16(sA + soff, Ag + (l_ga + (size_t)32 * it * 512 + kc * 64) * 2);
            cp_async16(sB + soff, Bg + (l_gb + (size_t)32 * it * 512 + kc * 64) * 2);
        }
        cp_commit();
    };

    load_chunk(sbase, 0);
    load_chunk(sbase + 32768, 1);

#pragma unroll
    for (int kc = 0; kc < 8; kc++) {
        const int stage = kc % 3;                       // compile-time
        const uint32_t sA = sbase + stage * 32768;      // immediate
        const uint32_t sB = sA + 16384;
        if (kc < 7) cp_wait<1>(); else cp_wait<0>();
        __syncthreads();
        if (kc + 2 < 8)
            load_chunk(sbase + ((kc + 2) % 3) * 32768, kc + 2);

#pragma unroll
        for (int ks = 0; ks < 4; ks++) {
            uint32_t a[4][4];
#pragma unroll
            for (int mt = 0; mt < 4; mt++) {
                int row = wm + mt * 16 + (lane & 15);
                int gr  = ks * 2 + (lane >> 4);
                ldsm_x4(a[mt], sA + row * 128 + (((uint32_t)gr ^ (row & 7)) << 4));
            }
            uint32_t b[2][4];
#pragma unroll
            for (int p = 0; p < 2; p++) {
                int nr = wn + p * 16 + (lane & 7) + ((lane >> 4) << 3);
                int gr = ks * 2 + ((lane >> 3) & 1);
                ldsm_x4(b[p], sB + nr * 128 + (((uint32_t)gr ^ (nr & 7)) << 4));
            }
#pragma unroll
            for (int mt = 0; mt < 4; mt++)
#pragma unroll
                for (int nt = 0; nt < 4; nt++)
                    mma16816(acc[mt][nt], a[mt], b[nt >> 1][(nt & 1) * 2],
                             b[nt >> 1][(nt & 1) * 2 + 1]);
        }
    }

    // ---- fused ArcNegFace epilogue (no bounds checks: n0+127 < NCLS) ----
#pragma unroll
    for (int mt = 0; mt < 4; mt++) {
        const int r0 = m0 + wm + mt * 16 + (lane >> 2);
        const int r1 = r0 + 8;
        const float tg0 = g_target[r0], tg1 = g_target[r1];
        const int lb0 = g_label[r0],  lb1 = g_label[r1];
        float* o0 = out + (size_t)r0 * NCLS;
        float* o1 = out + (size_t)r1 * NCLS;
#pragma unroll
        for (int nt = 0; nt < 4; nt++) {
            const int c0 = n0 + wn + nt * 8 + 2 * (lane & 3);
            float v[4];
#pragma unroll
            for (int i = 0; i < 4; i++) {
                const float cs  = acc[mt][nt][i];
                const float tg  = (i < 2) ? tg0 : tg1;
                const int   lb  = (i < 2) ? lb0 : lb1;
                const float dd  = cs - tg;
                const float ts  = C_ALPHA * __expf(-0.5f * dd * dd);
                float r = C_SCALE * (ts * cs + ts - 1.0f);
                if (c0 + (i & 1) == lb) r = C_SCALE * tg;
                v[i] = r;
            }
            *(float2*)(o0 + c0) = make_float2(v[0], v[1]);
            *(float2*)(o1 + c0) = make_float2(v[2], v[3]);
        }
    }

    // ---- produce next-wave B tile quarter (accumulators dead; L2-hot source) ----
    if (tp < NTILES) {
#pragma unroll
        for (int i = 0; i < 4; i++) {
            const int r = prow0 + wid * 4 + i;
            if (r < NCLS)
                norm_row_store((const float4*)(w + (size_t)r * 512),
                               g_Bh + (size_t)r * 512, lane);
        }
        __threadfence();
        __syncthreads();
        if (tid == 0) atomicAdd((int*)&g_flag[tp], 1);
    }
}

// ---------------- launcher (2 launches, single stream) ----------------
extern "C" void kernel_launch(void* const* d_in, const int* in_sizes, int n_in,
                              void* d_out, int out_size)
{
    const float* x     = (const float*)d_in[0];
    const int*   lraw  = (const int*)d_in[1];
    const float* w     = (const float*)d_in[2];
    float*       out   = (float*)d_out;

    cudaFuncSetAttribute(gemm_kernel, cudaFuncAttributeMaxDynamicSharedMemorySize, 98304);

    prep_kernel<<<PRENORM_CTAS + BATCH / 8, 256>>>(w, x, lraw);

    dim3 grid(4, NTILES);
    gemm_kernel<<<grid, 256, 98304>>>(w, out);
}